// round 3
// baseline (speedup 1.0000x reference)
#include <cuda_runtime.h>
#include <cstdint>

#define N_NODES 100000
#define N_EDGES 1600000
#define IN_F    512
#define OUT_F   64

// Scratch (allocation-free rule: __device__ globals)
__device__ float g_h[(size_t)N_NODES * OUT_F];   // projected features, 25.6 MB
__device__ float g_deg[N_NODES];                 // in-degree per dst node

// packed f32x2 FMA (Blackwell dual-rate fp32)
__device__ __forceinline__ void ffma2(unsigned long long& d,
                                      unsigned long long a,
                                      unsigned long long b) {
    asm("fma.rn.f32x2 %0, %1, %2, %0;" : "+l"(d) : "l"(a), "l"(b));
}
__device__ __forceinline__ void unpack2(float& lo, float& hi, unsigned long long v) {
    asm("mov.b64 {%0, %1}, %2;" : "=f"(lo), "=f"(hi) : "l"(v));
}

// ---------------------------------------------------------------------------
// 1) zero output accumulator + degree counters (vectorized)
// ---------------------------------------------------------------------------
__global__ void zero_kernel(float4* __restrict__ out4) {
    int i = blockIdx.x * blockDim.x + threadIdx.x;
    if (i < N_NODES * OUT_F / 4) out4[i] = make_float4(0.f, 0.f, 0.f, 0.f);
    if (i < N_NODES) g_deg[i] = 0.0f;
}

// ---------------------------------------------------------------------------
// 2) GEMM: g_h[100000,64] = feat[100000,512] @ W[512,64]
//    64x64 tile, BK=16, 256 threads. Inner loop in fma.rn.f32x2:
//    accumulators packed along M, B pre-duplicated in SMEM ({b,b} pairs).
// ---------------------------------------------------------------------------
__global__ __launch_bounds__(256) void gemm_kernel(
    const float* __restrict__ feat, const float* __restrict__ W)
{
    __shared__ float As[16][64];     // As[k][m]
    __shared__ float Bs2[16][128];   // Bs2[k][2n..2n+1] = {W[k][n], W[k][n]}

    const int tid = threadIdx.x;
    const int m0  = blockIdx.x * 64;
    const int tx  = tid & 15;        // n-tile (4 cols each)
    const int ty  = tid >> 4;        // m-tile (4 rows each)

    // feat loader: 64 rows x 16 k, float4 per thread
    const int lr = tid >> 2;
    const int lc = (tid & 3) * 4;
    // weight loader: 16 k x 64 n, float4 per thread, duplicated on store
    const int kw = tid >> 4;
    const int nw = (tid & 15) * 4;

    unsigned long long acc[2][4];
    #pragma unroll
    for (int i = 0; i < 2; i++)
        #pragma unroll
        for (int j = 0; j < 4; j++) acc[i][j] = 0ull;  // {0.f,0.f}

    for (int k0 = 0; k0 < IN_F; k0 += 16) {
        float4 fa = make_float4(0.f, 0.f, 0.f, 0.f);
        const int row = m0 + lr;
        if (row < N_NODES)
            fa = *reinterpret_cast<const float4*>(feat + (size_t)row * IN_F + k0 + lc);
        As[lc + 0][lr] = fa.x;
        As[lc + 1][lr] = fa.y;
        As[lc + 2][lr] = fa.z;
        As[lc + 3][lr] = fa.w;

        float4 wv = *reinterpret_cast<const float4*>(W + (size_t)(k0 + kw) * OUT_F + nw);
        *reinterpret_cast<float4*>(&Bs2[kw][nw * 2])     = make_float4(wv.x, wv.x, wv.y, wv.y);
        *reinterpret_cast<float4*>(&Bs2[kw][nw * 2 + 4]) = make_float4(wv.z, wv.z, wv.w, wv.w);

        __syncthreads();

        #pragma unroll
        for (int k = 0; k < 16; k++) {
            const ulonglong2 av  = *reinterpret_cast<const ulonglong2*>(&As[k][ty * 4]);
            const ulonglong2 bv0 = *reinterpret_cast<const ulonglong2*>(&Bs2[k][tx * 8]);
            const ulonglong2 bv1 = *reinterpret_cast<const ulonglong2*>(&Bs2[k][tx * 8 + 4]);
            ffma2(acc[0][0], av.x, bv0.x);
            ffma2(acc[0][1], av.x, bv0.y);
            ffma2(acc[0][2], av.x, bv1.x);
            ffma2(acc[0][3], av.x, bv1.y);
            ffma2(acc[1][0], av.y, bv0.x);
            ffma2(acc[1][1], av.y, bv0.y);
            ffma2(acc[1][2], av.y, bv1.x);
            ffma2(acc[1][3], av.y, bv1.y);
        }
        __syncthreads();
    }

    const int rbase = m0 + ty * 4;
    #pragma unroll
    for (int mp = 0; mp < 2; mp++) {
        float lo[4], hi[4];
        #pragma unroll
        for (int n = 0; n < 4; n++) unpack2(lo[n], hi[n], acc[mp][n]);
        const int r0 = rbase + mp * 2;
        if (r0 < N_NODES)
            *reinterpret_cast<float4*>(g_h + (size_t)r0 * OUT_F + tx * 4) =
                make_float4(lo[0], lo[1], lo[2], lo[3]);
        if (r0 + 1 < N_NODES)
            *reinterpret_cast<float4*>(g_h + (size_t)(r0 + 1) * OUT_F + tx * 4) =
                make_float4(hi[0], hi[1], hi[2], hi[3]);
    }
}

// ---------------------------------------------------------------------------
// 3) Edge scatter: out[dst] += h[src] * w  via vector reductions (no return).
//    16 threads per edge, float4 each (64 floats). deg[dst] += 1 once/edge.
// ---------------------------------------------------------------------------
__global__ __launch_bounds__(256) void edge_kernel(
    const int* __restrict__ src, const int* __restrict__ dst,
    const float* __restrict__ ew, float* __restrict__ out)
{
    const long long t = (long long)blockIdx.x * blockDim.x + threadIdx.x;
    const int e = (int)(t >> 4);
    const int l = (int)(t & 15);
    if (e >= N_EDGES) return;

    const int s = __ldg(src + e);
    const int d = __ldg(dst + e);
    const float w = __ldg(ew + e);

    float4 v = *reinterpret_cast<const float4*>(g_h + (size_t)s * OUT_F + l * 4);
    v.x *= w; v.y *= w; v.z *= w; v.w *= w;

    float* p = out + (size_t)d * OUT_F + l * 4;
    asm volatile("red.global.add.v4.f32 [%0], {%1,%2,%3,%4};"
                 :: "l"(p), "f"(v.x), "f"(v.y), "f"(v.z), "f"(v.w)
                 : "memory");

    if (l == 0) atomicAdd(&g_deg[d], 1.0f);
}

// ---------------------------------------------------------------------------
// 4) finalize: out = relu( (deg>0 ? msum/deg : 0) + bias )
// ---------------------------------------------------------------------------
__global__ void finalize_kernel(float* __restrict__ out, const float* __restrict__ bias) {
    const int i = blockIdx.x * blockDim.x + threadIdx.x;
    if (i >= N_NODES * OUT_F) return;
    const int node = i >> 6;
    const int c    = i & 63;
    const float d = g_deg[node];
    float v = out[i];
    v = (d > 0.0f) ? (v / d) : 0.0f;
    v += __ldg(bias + c);
    out[i] = fmaxf(v, 0.0f);
}

// ---------------------------------------------------------------------------
extern "C" void kernel_launch(void* const* d_in, const int* in_sizes, int n_in,
                              void* d_out, int out_size)
{
    const float* feat     = (const float*)d_in[0];
    const float* edge_w   = (const float*)d_in[1];
    const float* weight   = (const float*)d_in[2];
    const float* bias     = (const float*)d_in[3];
    const int*   edge_src = (const int*)d_in[4];
    const int*   edge_dst = (const int*)d_in[5];
    float* out = (float*)d_out;

    zero_kernel<<<(N_NODES * OUT_F / 4 + 255) / 256, 256>>>((float4*)out);
    gemm_kernel<<<(N_NODES + 63) / 64, 256>>>(feat, weight);
    edge_kernel<<<(int)(((long long)N_EDGES * 16 + 255) / 256), 256>>>(edge_src, edge_dst, edge_w, out);
    finalize_kernel<<<(N_NODES * OUT_F + 255) / 256, 256>>>(out, bias);
}

// round 4
// speedup vs baseline: 2.1247x; 2.1247x over previous
#include <cuda_runtime.h>
#include <cstdint>

#define N_NODES 100000
#define N_EDGES 1600000
#define IN_F    512
#define OUT_F   64

// Scratch (allocation-free rule: __device__ globals)
__device__ float g_h[(size_t)N_NODES * OUT_F];   // projected features, 25.6 MB
__device__ float g_deg[N_NODES];                 // in-degree per dst node

// ---------------------------------------------------------------------------
// tf32 helpers
// ---------------------------------------------------------------------------
__device__ __forceinline__ void split_tf32(float x, unsigned& big, unsigned& sml) {
    unsigned b;
    asm("cvt.rna.tf32.f32 %0, %1;" : "=r"(b) : "f"(x));
    float r = x - __uint_as_float(b);
    asm("cvt.rna.tf32.f32 %0, %1;" : "=r"(sml) : "f"(r));
    big = b;
}

__device__ __forceinline__ void mma8(float& d0, float& d1, float& d2, float& d3,
                                     unsigned a0, unsigned a1, unsigned a2, unsigned a3,
                                     unsigned b0, unsigned b1) {
    asm volatile("mma.sync.aligned.m16n8k8.row.col.f32.tf32.tf32.f32 "
                 "{%0,%1,%2,%3},{%4,%5,%6,%7},{%8,%9},{%0,%1,%2,%3};"
                 : "+f"(d0), "+f"(d1), "+f"(d2), "+f"(d3)
                 : "r"(a0), "r"(a1), "r"(a2), "r"(a3), "r"(b0), "r"(b1));
}

// ---------------------------------------------------------------------------
// 1) zero output accumulator + degree counters
// ---------------------------------------------------------------------------
__global__ void zero_kernel(float4* __restrict__ out4) {
    int i = blockIdx.x * blockDim.x + threadIdx.x;
    if (i < N_NODES * OUT_F / 4) out4[i] = make_float4(0.f, 0.f, 0.f, 0.f);
    if (i < N_NODES) g_deg[i] = 0.0f;
}

// ---------------------------------------------------------------------------
// 2) GEMM (tf32 tensor cores, 3xTF32 split):
//    g_h[100000,64] = feat[100000,512] @ W[512,64]
//    Block tile 128x64, 8 warps (4m x 2n), warp tile 32x32, KC=32.
// ---------------------------------------------------------------------------
__global__ __launch_bounds__(256) void gemm_tf32_kernel(
    const float* __restrict__ feat, const float* __restrict__ W)
{
    __shared__ float As[128][36];   // [m][k], padded (bank shift 4/row)
    __shared__ float Bs[32][68];    // [k][n], padded

    const int tid  = threadIdx.x;
    const int wid  = tid >> 5;
    const int lane = tid & 31;
    const int wm   = wid >> 1;      // 0..3  (m: 4 x 32)
    const int wn   = wid & 1;       // 0..1  (n: 2 x 32)
    const int gid  = lane >> 2;     // 0..7
    const int tig  = lane & 3;      // 0..3
    const int m0   = blockIdx.x * 128;

    float acc[2][4][4] = {};        // [mf][nf][reg]

    for (int k0 = 0; k0 < IN_F; k0 += 32) {
        // load A tile: 128 x 32 floats (1024 float4, 4 per thread)
        #pragma unroll
        for (int i = tid; i < 128 * 8; i += 256) {
            const int r  = i >> 3;
            const int c4 = (i & 7) * 4;
            float4 v = make_float4(0.f, 0.f, 0.f, 0.f);
            if (m0 + r < N_NODES)
                v = *reinterpret_cast<const float4*>(feat + (size_t)(m0 + r) * IN_F + k0 + c4);
            *reinterpret_cast<float4*>(&As[r][c4]) = v;
        }
        // load B tile: 32 x 64 floats (512 float4, 2 per thread)
        #pragma unroll
        for (int i = tid; i < 32 * 16; i += 256) {
            const int r  = i >> 4;
            const int c4 = (i & 15) * 4;
            float4 v = *reinterpret_cast<const float4*>(W + (size_t)(k0 + r) * OUT_F + c4);
            *reinterpret_cast<float4*>(&Bs[r][c4]) = v;
        }
        __syncthreads();

        #pragma unroll
        for (int kf = 0; kf < 4; kf++) {
            // A fragments (+ split)
            unsigned ab[2][4], al[2][4];
            #pragma unroll
            for (int mf = 0; mf < 2; mf++) {
                const int r = wm * 32 + mf * 16 + gid;
                const int c = kf * 8 + tig;
                split_tf32(As[r][c],         ab[mf][0], al[mf][0]);
                split_tf32(As[r + 8][c],     ab[mf][1], al[mf][1]);
                split_tf32(As[r][c + 4],     ab[mf][2], al[mf][2]);
                split_tf32(As[r + 8][c + 4], ab[mf][3], al[mf][3]);
            }
            // B fragments (+ split)
            unsigned bb[4][2], bl[4][2];
            #pragma unroll
            for (int nf = 0; nf < 4; nf++) {
                const int c = wn * 32 + nf * 8 + gid;
                const int r = kf * 8 + tig;
                split_tf32(Bs[r][c],     bb[nf][0], bl[nf][0]);
                split_tf32(Bs[r + 4][c], bb[nf][1], bl[nf][1]);
            }
            // 3xTF32: big*big + big*small + small*big
            #pragma unroll
            for (int mf = 0; mf < 2; mf++)
                #pragma unroll
                for (int nf = 0; nf < 4; nf++) {
                    float* d = acc[mf][nf];
                    mma8(d[0], d[1], d[2], d[3],
                         ab[mf][0], ab[mf][1], ab[mf][2], ab[mf][3],
                         bb[nf][0], bb[nf][1]);
                    mma8(d[0], d[1], d[2], d[3],
                         ab[mf][0], ab[mf][1], ab[mf][2], ab[mf][3],
                         bl[nf][0], bl[nf][1]);
                    mma8(d[0], d[1], d[2], d[3],
                         al[mf][0], al[mf][1], al[mf][2], al[mf][3],
                         bb[nf][0], bb[nf][1]);
                }
        }
        __syncthreads();
    }

    // store D fragments: d0,d1 -> (g, 2t..2t+1); d2,d3 -> (g+8, ...)
    #pragma unroll
    for (int mf = 0; mf < 2; mf++) {
        #pragma unroll
        for (int nf = 0; nf < 4; nf++) {
            const int c  = wn * 32 + nf * 8 + tig * 2;
            const int r0 = m0 + wm * 32 + mf * 16 + gid;
            if (r0 < N_NODES)
                *reinterpret_cast<float2*>(g_h + (size_t)r0 * OUT_F + c) =
                    make_float2(acc[mf][nf][0], acc[mf][nf][1]);
            if (r0 + 8 < N_NODES)
                *reinterpret_cast<float2*>(g_h + (size_t)(r0 + 8) * OUT_F + c) =
                    make_float2(acc[mf][nf][2], acc[mf][nf][3]);
        }
    }
}

// ---------------------------------------------------------------------------
// 3) Edge scatter: out[dst] += h[src] * w  via vector reductions (no return).
// ---------------------------------------------------------------------------
__global__ __launch_bounds__(256) void edge_kernel(
    const int* __restrict__ src, const int* __restrict__ dst,
    const float* __restrict__ ew, float* __restrict__ out)
{
    const long long t = (long long)blockIdx.x * blockDim.x + threadIdx.x;
    const int e = (int)(t >> 4);
    const int l = (int)(t & 15);
    if (e >= N_EDGES) return;

    const int s = __ldg(src + e);
    const int d = __ldg(dst + e);
    const float w = __ldg(ew + e);

    float4 v = *reinterpret_cast<const float4*>(g_h + (size_t)s * OUT_F + l * 4);
    v.x *= w; v.y *= w; v.z *= w; v.w *= w;

    float* p = out + (size_t)d * OUT_F + l * 4;
    asm volatile("red.global.add.v4.f32 [%0], {%1,%2,%3,%4};"
                 :: "l"(p), "f"(v.x), "f"(v.y), "f"(v.z), "f"(v.w)
                 : "memory");

    if (l == 0) atomicAdd(&g_deg[d], 1.0f);
}

// ---------------------------------------------------------------------------
// 4) finalize: out = relu( (deg>0 ? msum/deg : 0) + bias )
// ---------------------------------------------------------------------------
__global__ void finalize_kernel(float* __restrict__ out, const float* __restrict__ bias) {
    const int i = blockIdx.x * blockDim.x + threadIdx.x;
    if (i >= N_NODES * OUT_F) return;
    const int node = i >> 6;
    const int c    = i & 63;
    const float d = g_deg[node];
    float v = out[i];
    v = (d > 0.0f) ? (v / d) : 0.0f;
    v += __ldg(bias + c);
    out[i] = fmaxf(v, 0.0f);
}

// ---------------------------------------------------------------------------
extern "C" void kernel_launch(void* const* d_in, const int* in_sizes, int n_in,
                              void* d_out, int out_size)
{
    const float* feat     = (const float*)d_in[0];
    const float* edge_w   = (const float*)d_in[1];
    const float* weight   = (const float*)d_in[2];
    const float* bias     = (const float*)d_in[3];
    const int*   edge_src = (const int*)d_in[4];
    const int*   edge_dst = (const int*)d_in[5];
    float* out = (float*)d_out;

    zero_kernel<<<(N_NODES * OUT_F / 4 + 255) / 256, 256>>>((float4*)out);
    gemm_tf32_kernel<<<(N_NODES + 127) / 128, 256>>>(feat, weight);
    edge_kernel<<<(int)(((long long)N_EDGES * 16 + 255) / 256), 256>>>(edge_src, edge_dst, edge_w, out);
    finalize_kernel<<<(N_NODES * OUT_F + 255) / 256, 256>>>(out, bias);
}